// round 14
// baseline (speedup 1.0000x reference)
#include <cuda_runtime.h>
#include <cuda_bf16.h>
#include <mma.h>
using namespace nvcuda;

#define N_NODES   100000
#define N_EDGES   1600000
#define D         128
#define N_GRAPHS  512
#define N_CLASSES 10
#define SCAN_B    512
#define N_SCANBLK ((N_NODES + SCAN_B - 1) / SCAN_B)   // 196
#define M_BLK     64
#define KC        64
#define N_PAD     64

// -------- scratch: __device__ globals, referenced ONLY inside device code --------
// Self-cleaning protocol (graph-replay safe): g_deg/g_cnt are zeroed by k_scan1
// after being consumed; g_sums/g_cnts zeroed by k_scan2 before k_scan3 counts.
__device__ __nv_bfloat16  g_hh[(N_NODES + N_PAD) * D];  // h hi (bf16)
__device__ __nv_bfloat16  g_hl[(N_NODES + N_PAD) * D];  // h lo (bf16 residual)
__device__ __nv_bfloat16  g_xh[(N_NODES + N_PAD) * D];  // activation hi
__device__ __nv_bfloat16  g_xl[(N_NODES + N_PAD) * D];  // activation lo
__device__ float g_dinv[N_NODES];
__device__ int   g_deg[N_NODES];
__device__ int   g_cnt[N_NODES];
__device__ int   g_rowex[N_NODES];
__device__ int   g_row[N_NODES + 1];
__device__ int   g_bsum[N_SCANBLK];
__device__ int   g_boff[N_SCANBLK];
__device__ int   g_csr_src[N_EDGES];
__device__ float g_csr_nrm[N_EDGES];
__device__ float g_sums[N_GRAPHS * D];
__device__ float g_cnts[N_GRAPHS];

// ----------------- setup -----------------
__global__ __launch_bounds__(256) void k_count_deg(const int* __restrict__ dst) {
    int e = blockIdx.x * blockDim.x + threadIdx.x;
    if (e < N_EDGES) atomicAdd(&g_deg[dst[e]], 1);
}
// scan stage 1 + dinv; consumes g_deg then zeroes g_deg/g_cnt for next replay
__global__ __launch_bounds__(SCAN_B) void k_scan1() {
    __shared__ int s[SCAN_B];
    int tid = threadIdx.x;
    int gid = blockIdx.x * SCAN_B + tid;
    int v = (gid < N_NODES) ? g_deg[gid] : 0;
    if (gid < N_NODES) {
        g_dinv[gid] = rsqrtf((float)v + 1.0f);
        g_deg[gid] = 0;      // self-clean for next replay
        g_cnt[gid] = 0;      // fill cursor (used later this replay by k_fill)
    }
    s[tid] = v;
    __syncthreads();
    #pragma unroll
    for (int off = 1; off < SCAN_B; off <<= 1) {
        int t = (tid >= off) ? s[tid - off] : 0;
        __syncthreads();
        s[tid] += t;
        __syncthreads();
    }
    if (gid < N_NODES) g_rowex[gid] = s[tid] - v;
    if (tid == SCAN_B - 1) g_bsum[blockIdx.x] = s[tid];
}
// parallel scan of block sums + zero pool buffers (runs before k_scan3's counts)
__global__ __launch_bounds__(256) void k_scan2() {
    __shared__ int s[256];
    int tid = threadIdx.x;
    int v = (tid < N_SCANBLK) ? g_bsum[tid] : 0;
    s[tid] = v;
    __syncthreads();
    #pragma unroll
    for (int off = 1; off < 256; off <<= 1) {
        int t = (tid >= off) ? s[tid - off] : 0;
        __syncthreads();
        s[tid] += t;
        __syncthreads();
    }
    if (tid < N_SCANBLK) g_boff[tid] = s[tid] - v;
    if (tid == 255) g_row[N_NODES] = s[255];
    for (int i = tid; i < N_GRAPHS * D; i += 256) g_sums[i] = 0.f;
    for (int i = tid; i < N_GRAPHS; i += 256) g_cnts[i] = 0.f;
}
__global__ __launch_bounds__(256) void k_scan3(const int* __restrict__ batch) {
    int i = blockIdx.x * blockDim.x + threadIdx.x;
    if (i < N_NODES) {
        g_row[i] = g_rowex[i] + g_boff[i / SCAN_B];
        atomicAdd(&g_cnts[batch[i]], 1.0f);
    }
}
__global__ __launch_bounds__(256) void k_fill(const int* __restrict__ src,
                                              const int* __restrict__ dst) {
    int e = blockIdx.x * blockDim.x + threadIdx.x;
    if (e >= N_EDGES) return;
    int s = src[e], d = dst[e];
    int idx = g_row[d] + atomicAdd(&g_cnt[d], 1);
    g_csr_src[idx] = s;
    g_csr_nrm[idx] = g_dinv[s] * g_dinv[d];
}
__global__ __launch_bounds__(256) void k_cvt_x(const float* __restrict__ x) {
    int i = blockIdx.x * blockDim.x + threadIdx.x;
    if (i >= N_NODES * D) return;
    float v = x[i];
    __nv_bfloat16 h = __float2bfloat16(v);
    g_xh[i] = h;
    g_xl[i] = __float2bfloat16(v - __bfloat162float(h));
}

// ----------------- helpers -----------------
__device__ __forceinline__ __nv_bfloat16 cvt_hi(float v) { return __float2bfloat16(v); }
__device__ __forceinline__ __nv_bfloat16 cvt_lo(float v) {
    __nv_bfloat16 h = __float2bfloat16(v);
    return __float2bfloat16(v - __bfloat162float(h));
}
__device__ __forceinline__ float4 bf4_to_f4(uint2 u) {
    __nv_bfloat162 a = *(__nv_bfloat162*)&u.x;
    __nv_bfloat162 b = *(__nv_bfloat162*)&u.y;
    float2 fa = __bfloat1622float2(a);
    float2 fb = __bfloat1622float2(b);
    return make_float4(fa.x, fa.y, fb.x, fb.y);
}

// ----------------- tensor-core GEMM: h = X @ W, split-bf16, bf16 hi/lo output --------
#define SMEM_BYTES 33792
__global__ __launch_bounds__(256) void k_gemm_tc(const float* __restrict__ Wf) {
    __shared__ __align__(16) char smem_raw[SMEM_BYTES];
    __nv_bfloat16* As = (__nv_bfloat16*)smem_raw;            // [64][KC+8]
    __nv_bfloat16* Bs = (__nv_bfloat16*)(smem_raw + M_BLK * (KC + 8) * 2);  // [64][D+8]
    float* Cs = (float*)smem_raw;                             // [64][D+4]
    const int tid = threadIdx.x;
    const int wid = tid >> 5;
    const int wm = wid & 1;
    const int wn = wid >> 1;
    const int row0 = blockIdx.x * M_BLK;

    wmma::fragment<wmma::accumulator, 16, 16, 16, float> acc[2][2];
    #pragma unroll
    for (int i = 0; i < 2; i++)
        #pragma unroll
        for (int j = 0; j < 2; j++)
            wmma::fill_fragment(acc[i][j], 0.0f);

    constexpr int ASRC[6] = {0, 1, 0, 1, 0, 0};
    constexpr int ACOL[6] = {0, 0, KC, KC, 0, KC};
    constexpr int BLO[6]  = {0, 0, 0, 0, 1, 1};
    constexpr int BROW[6] = {0, 0, KC, KC, 0, KC};
    constexpr int LDB[6]  = {1, 0, 1, 0, 1, 1};

    #pragma unroll
    for (int c = 0; c < 6; c++) {
        const __nv_bfloat16* Asrc = ASRC[c] ? g_xl : g_xh;

        __syncthreads();
        #pragma unroll
        for (int j = 0; j < 4; j++) {
            int idx = tid + j * 256;
            int r = idx >> 4, g = idx & 15;
            *(uint2*)&As[r * (KC + 8) + g * 4] =
                *(const uint2*)&Asrc[(size_t)(row0 + r) * D + ACOL[c] + g * 4];
        }
        if (LDB[c]) {
            #pragma unroll
            for (int j = 0; j < 8; j++) {
                int idx = tid + j * 256;
                int r = idx >> 5, g = idx & 31;
                float4 wv = *(const float4*)&Wf[(size_t)(BROW[c] + r) * D + g * 4];
                __nv_bfloat162 p0, p1;
                if (BLO[c]) {
                    p0 = __nv_bfloat162{cvt_lo(wv.x), cvt_lo(wv.y)};
                    p1 = __nv_bfloat162{cvt_lo(wv.z), cvt_lo(wv.w)};
                } else {
                    p0 = __nv_bfloat162{cvt_hi(wv.x), cvt_hi(wv.y)};
                    p1 = __nv_bfloat162{cvt_hi(wv.z), cvt_hi(wv.w)};
                }
                *(__nv_bfloat162*)&Bs[r * (D + 8) + g * 4]     = p0;
                *(__nv_bfloat162*)&Bs[r * (D + 8) + g * 4 + 2] = p1;
            }
        }
        __syncthreads();

        #pragma unroll
        for (int kk = 0; kk < KC / 16; kk++) {
            wmma::fragment<wmma::matrix_a, 16, 16, 16, __nv_bfloat16, wmma::row_major> af[2];
            wmma::fragment<wmma::matrix_b, 16, 16, 16, __nv_bfloat16, wmma::row_major> bf[2];
            #pragma unroll
            for (int i = 0; i < 2; i++)
                wmma::load_matrix_sync(af[i], &As[(wm * 32 + i * 16) * (KC + 8) + kk * 16], KC + 8);
            #pragma unroll
            for (int j = 0; j < 2; j++)
                wmma::load_matrix_sync(bf[j], &Bs[(kk * 16) * (D + 8) + wn * 32 + j * 16], D + 8);
            #pragma unroll
            for (int i = 0; i < 2; i++)
                #pragma unroll
                for (int j = 0; j < 2; j++)
                    wmma::mma_sync(acc[i][j], af[i], bf[j], acc[i][j]);
        }
    }

    // ---- epilogue: fp32 accum -> smem -> packed bf16 hi/lo global ----
    __syncthreads();
    #pragma unroll
    for (int i = 0; i < 2; i++)
        #pragma unroll
        for (int j = 0; j < 2; j++)
            wmma::store_matrix_sync(&Cs[(wm * 32 + i * 16) * (D + 4) + wn * 32 + j * 16],
                                    acc[i][j], D + 4, wmma::mem_row_major);
    __syncthreads();
    #pragma unroll
    for (int it = 0; it < 8; it++) {
        int idx = tid + it * 256;
        int r = idx >> 5, g = idx & 31;
        float4 v = *(const float4*)&Cs[r * (D + 4) + g * 4];
        __nv_bfloat16 hx = cvt_hi(v.x), hy = cvt_hi(v.y), hz = cvt_hi(v.z), hw = cvt_hi(v.w);
        __nv_bfloat162 ph0{hx, hy}, ph1{hz, hw};
        __nv_bfloat162 pl0{cvt_lo(v.x), cvt_lo(v.y)}, pl1{cvt_lo(v.z), cvt_lo(v.w)};
        uint2 uh, ul;
        uh.x = *(unsigned*)&ph0; uh.y = *(unsigned*)&ph1;
        ul.x = *(unsigned*)&pl0; ul.y = *(unsigned*)&pl1;
        *(uint2*)&g_hh[(size_t)(row0 + r) * D + g * 4] = uh;
        *(uint2*)&g_hl[(size_t)(row0 + r) * D + g * 4] = ul;
    }
}

// ----------------- fused aggregation (warp per node, bf16 neighbor gather) -----------------
template <int LAST>
__global__ __launch_bounds__(256) void k_gather(const float* __restrict__ b,
                                                const int* __restrict__ batch) {
    int node = (blockIdx.x * blockDim.x + threadIdx.x) >> 5;
    int lane = threadIdx.x & 31;
    if (node >= N_NODES) return;

    const uint2* hh = (const uint2*)g_hh;
    const uint2* hl = (const uint2*)g_hl;
    int beg = g_row[node];
    int end = g_row[node + 1];

    float dv = g_dinv[node];
    float d2 = dv * dv;
    float4 vh = bf4_to_f4(hh[(size_t)node * 32 + lane]);
    float4 vl = bf4_to_f4(hl[(size_t)node * 32 + lane]);
    float4 acc = make_float4(d2 * (vh.x + vl.x), d2 * (vh.y + vl.y),
                             d2 * (vh.z + vl.z), d2 * (vh.w + vl.w));

    int j = beg;
    int n4 = beg + ((end - beg) & ~3);
    for (; j < n4; j += 4) {
        int   s0 = __ldg(&g_csr_src[j]),     s1 = __ldg(&g_csr_src[j + 1]);
        int   s2 = __ldg(&g_csr_src[j + 2]), s3 = __ldg(&g_csr_src[j + 3]);
        float w0 = __ldg(&g_csr_nrm[j]),     w1 = __ldg(&g_csr_nrm[j + 1]);
        float w2 = __ldg(&g_csr_nrm[j + 2]), w3 = __ldg(&g_csr_nrm[j + 3]);
        float4 v0 = bf4_to_f4(hh[(size_t)s0 * 32 + lane]);
        float4 v1 = bf4_to_f4(hh[(size_t)s1 * 32 + lane]);
        float4 v2 = bf4_to_f4(hh[(size_t)s2 * 32 + lane]);
        float4 v3 = bf4_to_f4(hh[(size_t)s3 * 32 + lane]);
        acc.x += v0.x * w0; acc.y += v0.y * w0; acc.z += v0.z * w0; acc.w += v0.w * w0;
        acc.x += v1.x * w1; acc.y += v1.y * w1; acc.z += v1.z * w1; acc.w += v1.w * w1;
        acc.x += v2.x * w2; acc.y += v2.y * w2; acc.z += v2.z * w2; acc.w += v2.w * w2;
        acc.x += v3.x * w3; acc.y += v3.y * w3; acc.z += v3.z * w3; acc.w += v3.w * w3;
    }
    for (; j < end; j++) {
        int   s0 = __ldg(&g_csr_src[j]);
        float w0 = __ldg(&g_csr_nrm[j]);
        float4 v0 = bf4_to_f4(hh[(size_t)s0 * 32 + lane]);
        acc.x += v0.x * w0; acc.y += v0.y * w0; acc.z += v0.z * w0; acc.w += v0.w * w0;
    }

    float4 bb = ((const float4*)b)[lane];
    acc.x = fmaxf(acc.x + bb.x, 0.f);
    acc.y = fmaxf(acc.y + bb.y, 0.f);
    acc.z = fmaxf(acc.z + bb.z, 0.f);
    acc.w = fmaxf(acc.w + bb.w, 0.f);

    if (LAST) {
        int bg = __ldg(&batch[node]);
        float* sp = g_sums + (size_t)bg * D + lane * 4;
        atomicAdd(sp + 0, acc.x);
        atomicAdd(sp + 1, acc.y);
        atomicAdd(sp + 2, acc.z);
        atomicAdd(sp + 3, acc.w);
    } else {
        __nv_bfloat16 hx = cvt_hi(acc.x), hy = cvt_hi(acc.y);
        __nv_bfloat16 hz = cvt_hi(acc.z), hw = cvt_hi(acc.w);
        __nv_bfloat162* xh2 = (__nv_bfloat162*)g_xh;
        __nv_bfloat162* xl2 = (__nv_bfloat162*)g_xl;
        size_t base = (size_t)node * 64 + lane * 2;
        xh2[base + 0] = __nv_bfloat162{hx, hy};
        xh2[base + 1] = __nv_bfloat162{hz, hw};
        xl2[base + 0] = __nv_bfloat162{
            __float2bfloat16(acc.x - __bfloat162float(hx)),
            __float2bfloat16(acc.y - __bfloat162float(hy))};
        xl2[base + 1] = __nv_bfloat162{
            __float2bfloat16(acc.z - __bfloat162float(hz)),
            __float2bfloat16(acc.w - __bfloat162float(hw))};
    }
}

// ----------------- classifier -----------------
__global__ __launch_bounds__(128) void k_classify(const float* __restrict__ Wc,
                                                  const float* __restrict__ bc,
                                                  float* __restrict__ out) {
    __shared__ float s[N_CLASSES];
    int g = blockIdx.x;
    int tid = threadIdx.x;
    if (tid < N_CLASSES) s[tid] = 0.f;
    __syncthreads();
    float cnt = fmaxf(g_cnts[g], 1.0f);
    float p = g_sums[(size_t)g * D + tid] / cnt;
    #pragma unroll
    for (int c = 0; c < N_CLASSES; c++)
        atomicAdd(&s[c], p * Wc[tid * N_CLASSES + c]);
    __syncthreads();
    if (tid < N_CLASSES) out[g * N_CLASSES + tid] = s[tid] + bc[tid];
}

// ---------------------------------------------------------------
extern "C" void kernel_launch(void* const* d_in, const int* in_sizes, int n_in,
                              void* d_out, int out_size) {
    const float* x       = (const float*)d_in[0];
    const int*   e_src   = (const int*)d_in[1];
    const int*   e_dst   = (const int*)d_in[2];
    const int*   batch   = (const int*)d_in[3];
    const float* W0 = (const float*)d_in[4];  const float* b0 = (const float*)d_in[5];
    const float* W1 = (const float*)d_in[6];  const float* b1 = (const float*)d_in[7];
    const float* W2 = (const float*)d_in[8];  const float* b2 = (const float*)d_in[9];
    const float* Wc = (const float*)d_in[10]; const float* bc = (const float*)d_in[11];
    float* out = (float*)d_out;

    const int NB_N  = (N_NODES + 255) / 256;
    const int NB_E  = (N_EDGES + 255) / 256;
    const int NB_NW = (N_NODES * 32 + 255) / 256;
    const int NB_ND = (N_NODES * D + 255) / 256;
    const int gemm_grid = (N_NODES + M_BLK - 1) / M_BLK;   // 1563

    // Single stream, deterministic execution order. k_gemm_tc is the 4th
    // launch (execution index 3) so the harness's ncu window profiles it.
    k_cvt_x<<<NB_ND, 256>>>(x);               // 0
    k_count_deg<<<NB_E, 256>>>(e_dst);        // 1
    k_scan1<<<N_SCANBLK, SCAN_B>>>();         // 2  (also zeroes deg/cnt)
    k_gemm_tc<<<gemm_grid, 256>>>(W0);        // 3  <- profiled
    k_scan2<<<1, 256>>>();                    // 4  (also zeroes sums/cnts)
    k_scan3<<<NB_N, 256>>>(batch);            // 5
    k_fill<<<NB_E, 256>>>(e_src, e_dst);      // 6

    // ---- layer 0 aggregation ----
    k_gather<0><<<NB_NW, 256>>>(b0, nullptr); // 7
    // ---- layer 1 ----
    k_gemm_tc<<<gemm_grid, 256>>>(W1);        // 8
    k_gather<0><<<NB_NW, 256>>>(b1, nullptr); // 9
    // ---- layer 2 (fused mean-pool) ----
    k_gemm_tc<<<gemm_grid, 256>>>(W2);        // 10
    k_gather<1><<<NB_NW, 256>>>(b2, batch);   // 11

    // ---- classifier ----
    k_classify<<<N_GRAPHS, 128>>>(Wc, bc, out); // 12
}

// round 15
// speedup vs baseline: 1.1127x; 1.1127x over previous
#include <cuda_runtime.h>
#include <cuda_bf16.h>
#include <mma.h>
using namespace nvcuda;

#define N_NODES   100000
#define N_EDGES   1600000
#define D         128
#define N_GRAPHS  512
#define N_CLASSES 10
#define SCAN_B    512
#define N_SCANBLK ((N_NODES + SCAN_B - 1) / SCAN_B)   // 196
#define M_BLK     64
#define KC        64
#define N_PAD     64

// -------- scratch: __device__ globals, referenced ONLY inside device code --------
// Self-cleaning protocol (graph-replay safe): g_deg/g_cnt zeroed by k_scan1
// after consumption; g_sums/g_cnts zeroed by k_scan2 before k_scan3 counts.
__device__ __nv_bfloat16  g_hh[(N_NODES + N_PAD) * D];  // h hi (bf16)
__device__ __nv_bfloat16  g_hl[(N_NODES + N_PAD) * D];  // h lo (bf16 residual)
__device__ __nv_bfloat16  g_xh[(N_NODES + N_PAD) * D];  // activation hi
__device__ __nv_bfloat16  g_xl[(N_NODES + N_PAD) * D];  // activation lo
__device__ float g_dinv[N_NODES];
__device__ int   g_deg[N_NODES];
__device__ int   g_cnt[N_NODES];
__device__ int   g_rowex[N_NODES];
__device__ int   g_row[N_NODES + 1];
__device__ int   g_bsum[N_SCANBLK];
__device__ int   g_boff[N_SCANBLK];
__device__ int   g_csr_src[N_EDGES];
__device__ float g_csr_nrm[N_EDGES];
__device__ float g_sums[N_GRAPHS * D];
__device__ float g_cnts[N_GRAPHS];

// ----------------- setup -----------------
__global__ __launch_bounds__(256) void k_count_deg(const int* __restrict__ dst) {
    int e = blockIdx.x * blockDim.x + threadIdx.x;
    if (e < N_EDGES) atomicAdd(&g_deg[dst[e]], 1);
}
__global__ __launch_bounds__(SCAN_B) void k_scan1() {
    __shared__ int s[SCAN_B];
    int tid = threadIdx.x;
    int gid = blockIdx.x * SCAN_B + tid;
    int v = (gid < N_NODES) ? g_deg[gid] : 0;
    if (gid < N_NODES) {
        g_dinv[gid] = rsqrtf((float)v + 1.0f);
        g_deg[gid] = 0;
        g_cnt[gid] = 0;
    }
    s[tid] = v;
    __syncthreads();
    #pragma unroll
    for (int off = 1; off < SCAN_B; off <<= 1) {
        int t = (tid >= off) ? s[tid - off] : 0;
        __syncthreads();
        s[tid] += t;
        __syncthreads();
    }
    if (gid < N_NODES) g_rowex[gid] = s[tid] - v;
    if (tid == SCAN_B - 1) g_bsum[blockIdx.x] = s[tid];
}
__global__ __launch_bounds__(256) void k_scan2() {
    __shared__ int s[256];
    int tid = threadIdx.x;
    int v = (tid < N_SCANBLK) ? g_bsum[tid] : 0;
    s[tid] = v;
    __syncthreads();
    #pragma unroll
    for (int off = 1; off < 256; off <<= 1) {
        int t = (tid >= off) ? s[tid - off] : 0;
        __syncthreads();
        s[tid] += t;
        __syncthreads();
    }
    if (tid < N_SCANBLK) g_boff[tid] = s[tid] - v;
    if (tid == 255) g_row[N_NODES] = s[255];
    for (int i = tid; i < N_GRAPHS * D; i += 256) g_sums[i] = 0.f;
    for (int i = tid; i < N_GRAPHS; i += 256) g_cnts[i] = 0.f;
}
__global__ __launch_bounds__(256) void k_scan3(const int* __restrict__ batch) {
    int i = blockIdx.x * blockDim.x + threadIdx.x;
    if (i < N_NODES) {
        g_row[i] = g_rowex[i] + g_boff[i / SCAN_B];
        atomicAdd(&g_cnts[batch[i]], 1.0f);
    }
}
__global__ __launch_bounds__(256) void k_fill(const int* __restrict__ src,
                                              const int* __restrict__ dst) {
    int e = blockIdx.x * blockDim.x + threadIdx.x;
    if (e >= N_EDGES) return;
    int s = src[e], d = dst[e];
    int idx = g_row[d] + atomicAdd(&g_cnt[d], 1);
    g_csr_src[idx] = s;
    g_csr_nrm[idx] = g_dinv[s] * g_dinv[d];
}
__global__ __launch_bounds__(256) void k_cvt_x(const float* __restrict__ x) {
    int i = blockIdx.x * blockDim.x + threadIdx.x;
    if (i >= N_NODES * D) return;
    float v = x[i];
    __nv_bfloat16 h = __float2bfloat16(v);
    g_xh[i] = h;
    g_xl[i] = __float2bfloat16(v - __bfloat162float(h));
}

// ----------------- helpers -----------------
__device__ __forceinline__ __nv_bfloat16 cvt_hi(float v) { return __float2bfloat16(v); }
__device__ __forceinline__ __nv_bfloat16 cvt_lo(float v) {
    __nv_bfloat16 h = __float2bfloat16(v);
    return __float2bfloat16(v - __bfloat162float(h));
}
__device__ __forceinline__ float4 bf4_to_f4(uint2 u) {
    __nv_bfloat162 a = *(__nv_bfloat162*)&u.x;
    __nv_bfloat162 b = *(__nv_bfloat162*)&u.y;
    float2 fa = __bfloat1622float2(a);
    float2 fb = __bfloat1622float2(b);
    return make_float4(fa.x, fa.y, fb.x, fb.y);
}

// ----------------- tensor-core GEMM: h = X @ W, split-bf16, bf16 hi/lo output --------
// R15 fix: __launch_bounds__(256,2) caps regs at 128 -> 2 CTAs/SM (was 255 regs,
// 1 CTA/SM, 12.4% occ, tensor 18%). Stage loop rolled (#pragma unroll 1) with
// branch arithmetic instead of constexpr tables to stop ptxas hoisting all six
// stages' staging state into live registers.
#define SMEM_BYTES 33792
__global__ __launch_bounds__(256, 2) void k_gemm_tc(const float* __restrict__ Wf) {
    __shared__ __align__(16) char smem_raw[SMEM_BYTES];
    __nv_bfloat16* As = (__nv_bfloat16*)smem_raw;            // [64][KC+8]
    __nv_bfloat16* Bs = (__nv_bfloat16*)(smem_raw + M_BLK * (KC + 8) * 2);  // [64][D+8]
    float* Cs = (float*)smem_raw;                             // [64][D+4]
    const int tid = threadIdx.x;
    const int wid = tid >> 5;
    const int wm = wid & 1;
    const int wn = wid >> 1;
    const int row0 = blockIdx.x * M_BLK;

    wmma::fragment<wmma::accumulator, 16, 16, 16, float> acc[2][2];
    #pragma unroll
    for (int i = 0; i < 2; i++)
        #pragma unroll
        for (int j = 0; j < 2; j++)
            wmma::fill_fragment(acc[i][j], 0.0f);

    // stages: 0:(xh0,Wh0) 1:(xl0,Wh0) 2:(xh1,Wh1) 3:(xl1,Wh1) 4:(xh0,Wl0) 5:(xh1,Wl1)
    #pragma unroll 1
    for (int c = 0; c < 6; c++) {
        const bool a_lo = (c == 1) || (c == 3);
        const int  koff = ((c == 2) || (c == 3) || (c == 5)) ? KC : 0;
        const bool ldb  = !a_lo;               // B reused across (xh,xl) pairs
        const bool blo  = (c >= 4);
        const __nv_bfloat16* Asrc = a_lo ? g_xl : g_xh;

        __syncthreads();
        #pragma unroll
        for (int j = 0; j < 4; j++) {
            int idx = tid + j * 256;
            int r = idx >> 4, g = idx & 15;
            *(uint2*)&As[r * (KC + 8) + g * 4] =
                *(const uint2*)&Asrc[(size_t)(row0 + r) * D + koff + g * 4];
        }
        if (ldb) {
            #pragma unroll
            for (int j = 0; j < 8; j++) {
                int idx = tid + j * 256;
                int r = idx >> 5, g = idx & 31;
                float4 wv = *(const float4*)&Wf[(size_t)(koff + r) * D + g * 4];
                __nv_bfloat162 p0, p1;
                if (blo) {
                    p0 = __nv_bfloat162{cvt_lo(wv.x), cvt_lo(wv.y)};
                    p1 = __nv_bfloat162{cvt_lo(wv.z), cvt_lo(wv.w)};
                } else {
                    p0 = __nv_bfloat162{cvt_hi(wv.x), cvt_hi(wv.y)};
                    p1 = __nv_bfloat162{cvt_hi(wv.z), cvt_hi(wv.w)};
                }
                *(__nv_bfloat162*)&Bs[r * (D + 8) + g * 4]     = p0;
                *(__nv_bfloat162*)&Bs[r * (D + 8) + g * 4 + 2] = p1;
            }
        }
        __syncthreads();

        #pragma unroll
        for (int kk = 0; kk < KC / 16; kk++) {
            wmma::fragment<wmma::matrix_a, 16, 16, 16, __nv_bfloat16, wmma::row_major> af[2];
            wmma::fragment<wmma::matrix_b, 16, 16, 16, __nv_bfloat16, wmma::row_major> bf[2];
            #pragma unroll
            for (int i = 0; i < 2; i++)
                wmma::load_matrix_sync(af[i], &As[(wm * 32 + i * 16) * (KC + 8) + kk * 16], KC + 8);
            #pragma unroll
            for (int j = 0; j < 2; j++)
                wmma::load_matrix_sync(bf[j], &Bs[(kk * 16) * (D + 8) + wn * 32 + j * 16], D + 8);
            #pragma unroll
            for (int i = 0; i < 2; i++)
                #pragma unroll
                for (int j = 0; j < 2; j++)
                    wmma::mma_sync(acc[i][j], af[i], bf[j], acc[i][j]);
        }
    }

    // ---- epilogue: fp32 accum -> smem -> packed bf16 hi/lo global ----
    __syncthreads();
    #pragma unroll
    for (int i = 0; i < 2; i++)
        #pragma unroll
        for (int j = 0; j < 2; j++)
            wmma::store_matrix_sync(&Cs[(wm * 32 + i * 16) * (D + 4) + wn * 32 + j * 16],
                                    acc[i][j], D + 4, wmma::mem_row_major);
    __syncthreads();
    #pragma unroll
    for (int it = 0; it < 8; it++) {
        int idx = tid + it * 256;
        int r = idx >> 5, g = idx & 31;
        float4 v = *(const float4*)&Cs[r * (D + 4) + g * 4];
        __nv_bfloat16 hx = cvt_hi(v.x), hy = cvt_hi(v.y), hz = cvt_hi(v.z), hw = cvt_hi(v.w);
        __nv_bfloat162 ph0{hx, hy}, ph1{hz, hw};
        __nv_bfloat162 pl0{cvt_lo(v.x), cvt_lo(v.y)}, pl1{cvt_lo(v.z), cvt_lo(v.w)};
        uint2 uh, ul;
        uh.x = *(unsigned*)&ph0; uh.y = *(unsigned*)&ph1;
        ul.x = *(unsigned*)&pl0; ul.y = *(unsigned*)&pl1;
        *(uint2*)&g_hh[(size_t)(row0 + r) * D + g * 4] = uh;
        *(uint2*)&g_hl[(size_t)(row0 + r) * D + g * 4] = ul;
    }
}

// ----------------- fused aggregation (warp per node, bf16 neighbor gather) -----------------
template <int LAST>
__global__ __launch_bounds__(256) void k_gather(const float* __restrict__ b,
                                                const int* __restrict__ batch) {
    int node = (blockIdx.x * blockDim.x + threadIdx.x) >> 5;
    int lane = threadIdx.x & 31;
    if (node >= N_NODES) return;

    const uint2* hh = (const uint2*)g_hh;
    const uint2* hl = (const uint2*)g_hl;
    int beg = g_row[node];
    int end = g_row[node + 1];

    float dv = g_dinv[node];
    float d2 = dv * dv;
    float4 vh = bf4_to_f4(hh[(size_t)node * 32 + lane]);
    float4 vl = bf4_to_f4(hl[(size_t)node * 32 + lane]);
    float4 acc = make_float4(d2 * (vh.x + vl.x), d2 * (vh.y + vl.y),
                             d2 * (vh.z + vl.z), d2 * (vh.w + vl.w));

    int j = beg;
    int n4 = beg + ((end - beg) & ~3);
    for (; j < n4; j += 4) {
        int   s0 = __ldg(&g_csr_src[j]),     s1 = __ldg(&g_csr_src[j + 1]);
        int   s2 = __ldg(&g_csr_src[j + 2]), s3 = __ldg(&g_csr_src[j + 3]);
        float w0 = __ldg(&g_csr_nrm[j]),     w1 = __ldg(&g_csr_nrm[j + 1]);
        float w2 = __ldg(&g_csr_nrm[j + 2]), w3 = __ldg(&g_csr_nrm[j + 3]);
        float4 v0 = bf4_to_f4(hh[(size_t)s0 * 32 + lane]);
        float4 v1 = bf4_to_f4(hh[(size_t)s1 * 32 + lane]);
        float4 v2 = bf4_to_f4(hh[(size_t)s2 * 32 + lane]);
        float4 v3 = bf4_to_f4(hh[(size_t)s3 * 32 + lane]);
        acc.x += v0.x * w0; acc.y += v0.y * w0; acc.z += v0.z * w0; acc.w += v0.w * w0;
        acc.x += v1.x * w1; acc.y += v1.y * w1; acc.z += v1.z * w1; acc.w += v1.w * w1;
        acc.x += v2.x * w2; acc.y += v2.y * w2; acc.z += v2.z * w2; acc.w += v2.w * w2;
        acc.x += v3.x * w3; acc.y += v3.y * w3; acc.z += v3.z * w3; acc.w += v3.w * w3;
    }
    for (; j < end; j++) {
        int   s0 = __ldg(&g_csr_src[j]);
        float w0 = __ldg(&g_csr_nrm[j]);
        float4 v0 = bf4_to_f4(hh[(size_t)s0 * 32 + lane]);
        acc.x += v0.x * w0; acc.y += v0.y * w0; acc.z += v0.z * w0; acc.w += v0.w * w0;
    }

    float4 bb = ((const float4*)b)[lane];
    acc.x = fmaxf(acc.x + bb.x, 0.f);
    acc.y = fmaxf(acc.y + bb.y, 0.f);
    acc.z = fmaxf(acc.z + bb.z, 0.f);
    acc.w = fmaxf(acc.w + bb.w, 0.f);

    if (LAST) {
        int bg = __ldg(&batch[node]);
        float* sp = g_sums + (size_t)bg * D + lane * 4;
        atomicAdd(sp + 0, acc.x);
        atomicAdd(sp + 1, acc.y);
        atomicAdd(sp + 2, acc.z);
        atomicAdd(sp + 3, acc.w);
    } else {
        __nv_bfloat16 hx = cvt_hi(acc.x), hy = cvt_hi(acc.y);
        __nv_bfloat16 hz = cvt_hi(acc.z), hw = cvt_hi(acc.w);
        __nv_bfloat162* xh2 = (__nv_bfloat162*)g_xh;
        __nv_bfloat162* xl2 = (__nv_bfloat162*)g_xl;
        size_t base = (size_t)node * 64 + lane * 2;
        xh2[base + 0] = __nv_bfloat162{hx, hy};
        xh2[base + 1] = __nv_bfloat162{hz, hw};
        xl2[base + 0] = __nv_bfloat162{
            __float2bfloat16(acc.x - __bfloat162float(hx)),
            __float2bfloat16(acc.y - __bfloat162float(hy))};
        xl2[base + 1] = __nv_bfloat162{
            __float2bfloat16(acc.z - __bfloat162float(hz)),
            __float2bfloat16(acc.w - __bfloat162float(hw))};
    }
}

// ----------------- classifier -----------------
__global__ __launch_bounds__(128) void k_classify(const float* __restrict__ Wc,
                                                  const float* __restrict__ bc,
                                                  float* __restrict__ out) {
    __shared__ float s[N_CLASSES];
    int g = blockIdx.x;
    int tid = threadIdx.x;
    if (tid < N_CLASSES) s[tid] = 0.f;
    __syncthreads();
    float cnt = fmaxf(g_cnts[g], 1.0f);
    float p = g_sums[(size_t)g * D + tid] / cnt;
    #pragma unroll
    for (int c = 0; c < N_CLASSES; c++)
        atomicAdd(&s[c], p * Wc[tid * N_CLASSES + c]);
    __syncthreads();
    if (tid < N_CLASSES) out[g * N_CLASSES + tid] = s[tid] + bc[tid];
}

// ---------------------------------------------------------------
extern "C" void kernel_launch(void* const* d_in, const int* in_sizes, int n_in,
                              void* d_out, int out_size) {
    const float* x       = (const float*)d_in[0];
    const int*   e_src   = (const int*)d_in[1];
    const int*   e_dst   = (const int*)d_in[2];
    const int*   batch   = (const int*)d_in[3];
    const float* W0 = (const float*)d_in[4];  const float* b0 = (const float*)d_in[5];
    const float* W1 = (const float*)d_in[6];  const float* b1 = (const float*)d_in[7];
    const float* W2 = (const float*)d_in[8];  const float* b2 = (const float*)d_in[9];
    const float* Wc = (const float*)d_in[10]; const float* bc = (const float*)d_in[11];
    float* out = (float*)d_out;

    const int NB_N  = (N_NODES + 255) / 256;
    const int NB_E  = (N_EDGES + 255) / 256;
    const int NB_NW = (N_NODES * 32 + 255) / 256;
    const int NB_ND = (N_NODES * D + 255) / 256;
    const int gemm_grid = (N_NODES + M_BLK - 1) / M_BLK;   // 1563

    // Single stream; k_gemm_tc stays at execution index 3 for ncu verification.
    k_cvt_x<<<NB_ND, 256>>>(x);               // 0
    k_count_deg<<<NB_E, 256>>>(e_dst);        // 1
    k_scan1<<<N_SCANBLK, SCAN_B>>>();         // 2
    k_gemm_tc<<<gemm_grid, 256>>>(W0);        // 3  <- profiled
    k_scan2<<<1, 256>>>();                    // 4
    k_scan3<<<NB_N, 256>>>(batch);            // 5
    k_fill<<<NB_E, 256>>>(e_src, e_dst);      // 6

    // ---- layer 0 aggregation ----
    k_gather<0><<<NB_NW, 256>>>(b0, nullptr); // 7
    // ---- layer 1 ----
    k_gemm_tc<<<gemm_grid, 256>>>(W1);        // 8
    k_gather<0><<<NB_NW, 256>>>(b1, nullptr); // 9
    // ---- layer 2 (fused mean-pool) ----
    k_gemm_tc<<<gemm_grid, 256>>>(W2);        // 10
    k_gather<1><<<NB_NW, 256>>>(b2, batch);   // 11

    // ---- classifier ----
    k_classify<<<N_GRAPHS, 128>>>(Wc, bc, out); // 12
}

// round 16
// speedup vs baseline: 1.2887x; 1.1582x over previous
#include <cuda_runtime.h>
#include <cuda_bf16.h>
#include <mma.h>
using namespace nvcuda;

#define N_NODES   100000
#define N_EDGES   1600000
#define D         128
#define N_GRAPHS  512
#define N_CLASSES 10
#define SCAN_B    512
#define N_SCANBLK ((N_NODES + SCAN_B - 1) / SCAN_B)   // 196
#define M_BLK     64
#define KC        64
#define N_PAD     64

// -------- scratch: __device__ globals, referenced ONLY inside device code --------
// Self-cleaning protocol (graph-replay safe): g_deg/g_cnt zeroed by k_scan1
// after consumption; g_sums/g_cnts zeroed by k_scan2 before k_scan3 counts.
__device__ __nv_bfloat16  g_hh[(N_NODES + N_PAD) * D];  // h hi (bf16)
__device__ __nv_bfloat16  g_hl[(N_NODES + N_PAD) * D];  // h lo (bf16 residual)
__device__ __nv_bfloat16  g_xh[(N_NODES + N_PAD) * D];  // activation hi
__device__ __nv_bfloat16  g_xl[(N_NODES + N_PAD) * D];  // activation lo
__device__ float g_dinv[N_NODES];
__device__ int   g_deg[N_NODES];
__device__ int   g_cnt[N_NODES];
__device__ int   g_rowex[N_NODES];
__device__ int   g_row[N_NODES + 1];
__device__ int   g_bsum[N_SCANBLK];
__device__ int   g_boff[N_SCANBLK];
__device__ int   g_csr_src[N_EDGES];
__device__ float g_csr_nrm[N_EDGES];
__device__ float g_sums[N_GRAPHS * D];
__device__ float g_cnts[N_GRAPHS];

// ----------------- setup -----------------
__global__ __launch_bounds__(256) void k_count_deg(const int* __restrict__ dst) {
    int e = blockIdx.x * blockDim.x + threadIdx.x;
    if (e < N_EDGES) atomicAdd(&g_deg[dst[e]], 1);
}
__global__ __launch_bounds__(SCAN_B) void k_scan1() {
    __shared__ int s[SCAN_B];
    int tid = threadIdx.x;
    int gid = blockIdx.x * SCAN_B + tid;
    int v = (gid < N_NODES) ? g_deg[gid] : 0;
    if (gid < N_NODES) {
        g_dinv[gid] = rsqrtf((float)v + 1.0f);
        g_deg[gid] = 0;
        g_cnt[gid] = 0;
    }
    s[tid] = v;
    __syncthreads();
    #pragma unroll
    for (int off = 1; off < SCAN_B; off <<= 1) {
        int t = (tid >= off) ? s[tid - off] : 0;
        __syncthreads();
        s[tid] += t;
        __syncthreads();
    }
    if (gid < N_NODES) g_rowex[gid] = s[tid] - v;
    if (tid == SCAN_B - 1) g_bsum[blockIdx.x] = s[tid];
}
__global__ __launch_bounds__(256) void k_scan2() {
    __shared__ int s[256];
    int tid = threadIdx.x;
    int v = (tid < N_SCANBLK) ? g_bsum[tid] : 0;
    s[tid] = v;
    __syncthreads();
    #pragma unroll
    for (int off = 1; off < 256; off <<= 1) {
        int t = (tid >= off) ? s[tid - off] : 0;
        __syncthreads();
        s[tid] += t;
        __syncthreads();
    }
    if (tid < N_SCANBLK) g_boff[tid] = s[tid] - v;
    if (tid == 255) g_row[N_NODES] = s[255];
    for (int i = tid; i < N_GRAPHS * D; i += 256) g_sums[i] = 0.f;
    for (int i = tid; i < N_GRAPHS; i += 256) g_cnts[i] = 0.f;
}
__global__ __launch_bounds__(256) void k_scan3(const int* __restrict__ batch) {
    int i = blockIdx.x * blockDim.x + threadIdx.x;
    if (i < N_NODES) {
        g_row[i] = g_rowex[i] + g_boff[i / SCAN_B];
        atomicAdd(&g_cnts[batch[i]], 1.0f);
    }
}
__global__ __launch_bounds__(256) void k_fill(const int* __restrict__ src,
                                              const int* __restrict__ dst) {
    int e = blockIdx.x * blockDim.x + threadIdx.x;
    if (e >= N_EDGES) return;
    int s = src[e], d = dst[e];
    int idx = g_row[d] + atomicAdd(&g_cnt[d], 1);
    g_csr_src[idx] = s;
    g_csr_nrm[idx] = g_dinv[s] * g_dinv[d];
}

// ----------------- helpers -----------------
__device__ __forceinline__ __nv_bfloat16 cvt_hi(float v) { return __float2bfloat16(v); }
__device__ __forceinline__ __nv_bfloat16 cvt_lo(float v) {
    __nv_bfloat16 h = __float2bfloat16(v);
    return __float2bfloat16(v - __bfloat162float(h));
}
__device__ __forceinline__ float4 bf4_to_f4(uint2 u) {
    __nv_bfloat162 a = *(__nv_bfloat162*)&u.x;
    __nv_bfloat162 b = *(__nv_bfloat162*)&u.y;
    float2 fa = __bfloat1622float2(a);
    float2 fb = __bfloat1622float2(b);
    return make_float4(fa.x, fa.y, fb.x, fb.y);
}

// ----------------- tensor-core GEMM: h = X @ W, split-bf16, bf16 hi/lo output --------
// R16: dual A-buffer per K-half (Ah+Al staged together, B=Wh reused for both A
// passes, then restaged as Wl). 4 A-stagings / 8 syncs vs 6 / 12. SRC=0 stages A
// straight from fp32 x (kills k_cvt_x); SRC=1 reads g_xh/g_xl.
#define SMEM_BYTES 35840
__device__ __forceinline__ void mma_pass(
    const __nv_bfloat16* As, const __nv_bfloat16* Bs,
    wmma::fragment<wmma::accumulator, 16, 16, 16, float> (&acc)[2][2],
    int wm, int wn) {
    #pragma unroll
    for (int kk = 0; kk < KC / 16; kk++) {
        wmma::fragment<wmma::matrix_a, 16, 16, 16, __nv_bfloat16, wmma::row_major> af[2];
        wmma::fragment<wmma::matrix_b, 16, 16, 16, __nv_bfloat16, wmma::row_major> bf[2];
        #pragma unroll
        for (int i = 0; i < 2; i++)
            wmma::load_matrix_sync(af[i], &As[(wm * 32 + i * 16) * (KC + 8) + kk * 16], KC + 8);
        #pragma unroll
        for (int j = 0; j < 2; j++)
            wmma::load_matrix_sync(bf[j], &Bs[(kk * 16) * (D + 8) + wn * 32 + j * 16], D + 8);
        #pragma unroll
        for (int i = 0; i < 2; i++)
            #pragma unroll
            for (int j = 0; j < 2; j++)
                wmma::mma_sync(acc[i][j], af[i], bf[j], acc[i][j]);
    }
}

template <int SRC>
__global__ __launch_bounds__(256, 2) void k_gemm_tc(const float* __restrict__ xf,
                                                    const float* __restrict__ Wf) {
    __shared__ __align__(16) char smem_raw[SMEM_BYTES];
    __nv_bfloat16* Ah = (__nv_bfloat16*)smem_raw;             // [64][KC+8]  9216B
    __nv_bfloat16* Al = (__nv_bfloat16*)(smem_raw + 9216);    // [64][KC+8]  9216B
    __nv_bfloat16* Bs = (__nv_bfloat16*)(smem_raw + 18432);   // [64][D+8]  17408B
    float* Cs = (float*)smem_raw;                              // [64][D+4]  33792B (epilogue alias)
    const int tid = threadIdx.x;
    const int wid = tid >> 5;
    const int wm = wid & 1;
    const int wn = wid >> 1;
    const int row0 = blockIdx.x * M_BLK;

    wmma::fragment<wmma::accumulator, 16, 16, 16, float> acc[2][2];
    #pragma unroll
    for (int i = 0; i < 2; i++)
        #pragma unroll
        for (int j = 0; j < 2; j++)
            wmma::fill_fragment(acc[i][j], 0.0f);

    #pragma unroll 1
    for (int half = 0; half < 2; half++) {
        const int koff = half * KC;

        __syncthreads();
        // ---- stage A hi + lo together ----
        if (SRC == 0) {
            // from fp32 x: one read feeds both buffers. Guard last block (x unpadded).
            #pragma unroll
            for (int j = 0; j < 4; j++) {
                int idx = tid + j * 256;           // 0..1023
                int r = idx >> 4, g = idx & 15;    // row, float4 group (4 floats)
                int row = row0 + r;
                float4 xv = (row < N_NODES)
                    ? *(const float4*)&xf[(size_t)row * D + koff + g * 4]
                    : make_float4(0.f, 0.f, 0.f, 0.f);
                __nv_bfloat162 h0{cvt_hi(xv.x), cvt_hi(xv.y)}, h1{cvt_hi(xv.z), cvt_hi(xv.w)};
                __nv_bfloat162 l0{cvt_lo(xv.x), cvt_lo(xv.y)}, l1{cvt_lo(xv.z), cvt_lo(xv.w)};
                *(__nv_bfloat162*)&Ah[r * (KC + 8) + g * 4]     = h0;
                *(__nv_bfloat162*)&Ah[r * (KC + 8) + g * 4 + 2] = h1;
                *(__nv_bfloat162*)&Al[r * (KC + 8) + g * 4]     = l0;
                *(__nv_bfloat162*)&Al[r * (KC + 8) + g * 4 + 2] = l1;
            }
        } else {
            // from padded bf16 activations (pad rows hold stale-but-unread data)
            #pragma unroll
            for (int j = 0; j < 4; j++) {
                int idx = tid + j * 256;
                int r = idx >> 4, g = idx & 15;
                *(uint2*)&Ah[r * (KC + 8) + g * 4] =
                    *(const uint2*)&g_xh[(size_t)(row0 + r) * D + koff + g * 4];
                *(uint2*)&Al[r * (KC + 8) + g * 4] =
                    *(const uint2*)&g_xl[(size_t)(row0 + r) * D + koff + g * 4];
            }
        }
        // ---- stage B = Wh[koff] ----
        #pragma unroll
        for (int j = 0; j < 8; j++) {
            int idx = tid + j * 256;
            int r = idx >> 5, g = idx & 31;
            float4 wv = *(const float4*)&Wf[(size_t)(koff + r) * D + g * 4];
            *(__nv_bfloat162*)&Bs[r * (D + 8) + g * 4]     = __nv_bfloat162{cvt_hi(wv.x), cvt_hi(wv.y)};
            *(__nv_bfloat162*)&Bs[r * (D + 8) + g * 4 + 2] = __nv_bfloat162{cvt_hi(wv.z), cvt_hi(wv.w)};
        }
        __syncthreads();

        mma_pass(Ah, Bs, acc, wm, wn);   // Xh @ Wh
        mma_pass(Al, Bs, acc, wm, wn);   // Xl @ Wh

        __syncthreads();
        // ---- restage B = Wl[koff] ----
        #pragma unroll
        for (int j = 0; j < 8; j++) {
            int idx = tid + j * 256;
            int r = idx >> 5, g = idx & 31;
            float4 wv = *(const float4*)&Wf[(size_t)(koff + r) * D + g * 4];
            *(__nv_bfloat162*)&Bs[r * (D + 8) + g * 4]     = __nv_bfloat162{cvt_lo(wv.x), cvt_lo(wv.y)};
            *(__nv_bfloat162*)&Bs[r * (D + 8) + g * 4 + 2] = __nv_bfloat162{cvt_lo(wv.z), cvt_lo(wv.w)};
        }
        __syncthreads();

        mma_pass(Ah, Bs, acc, wm, wn);   // Xh @ Wl
    }

    // ---- epilogue: fp32 accum -> smem -> packed bf16 hi/lo global ----
    __syncthreads();
    #pragma unroll
    for (int i = 0; i < 2; i++)
        #pragma unroll
        for (int j = 0; j < 2; j++)
            wmma::store_matrix_sync(&Cs[(wm * 32 + i * 16) * (D + 4) + wn * 32 + j * 16],
                                    acc[i][j], D + 4, wmma::mem_row_major);
    __syncthreads();
    #pragma unroll
    for (int it = 0; it < 8; it++) {
        int idx = tid + it * 256;
        int r = idx >> 5, g = idx & 31;
        float4 v = *(const float4*)&Cs[r * (D + 4) + g * 4];
        __nv_bfloat16 hx = cvt_hi(v.x), hy = cvt_hi(v.y), hz = cvt_hi(v.z), hw = cvt_hi(v.w);
        __nv_bfloat162 ph0{hx, hy}, ph1{hz, hw};
        __nv_bfloat162 pl0{cvt_lo(v.x), cvt_lo(v.y)}, pl1{cvt_lo(v.z), cvt_lo(v.w)};
        uint2 uh, ul;
        uh.x = *(unsigned*)&ph0; uh.y = *(unsigned*)&ph1;
        ul.x = *(unsigned*)&pl0; ul.y = *(unsigned*)&pl1;
        *(uint2*)&g_hh[(size_t)(row0 + r) * D + g * 4] = uh;
        *(uint2*)&g_hl[(size_t)(row0 + r) * D + g * 4] = ul;
    }
}

// ----------------- fused aggregation (warp per node, bf16 neighbor gather) -----------------
template <int LAST>
__global__ __launch_bounds__(256) void k_gather(const float* __restrict__ b,
                                                const int* __restrict__ batch) {
    int node = (blockIdx.x * blockDim.x + threadIdx.x) >> 5;
    int lane = threadIdx.x & 31;
    if (node >= N_NODES) return;

    const uint2* hh = (const uint2*)g_hh;
    const uint2* hl = (const uint2*)g_hl;
    int beg = g_row[node];
    int end = g_row[node + 1];

    float dv = g_dinv[node];
    float d2 = dv * dv;
    float4 vh = bf4_to_f4(hh[(size_t)node * 32 + lane]);
    float4 vl = bf4_to_f4(hl[(size_t)node * 32 + lane]);
    float4 acc = make_float4(d2 * (vh.x + vl.x), d2 * (vh.y + vl.y),
                             d2 * (vh.z + vl.z), d2 * (vh.w + vl.w));

    int j = beg;
    int n4 = beg + ((end - beg) & ~3);
    for (; j < n4; j += 4) {
        int   s0 = __ldg(&g_csr_src[j]),     s1 = __ldg(&g_csr_src[j + 1]);
        int   s2 = __ldg(&g_csr_src[j + 2]), s3 = __ldg(&g_csr_src[j + 3]);
        float w0 = __ldg(&g_csr_nrm[j]),     w1 = __ldg(&g_csr_nrm[j + 1]);
        float w2 = __ldg(&g_csr_nrm[j + 2]), w3 = __ldg(&g_csr_nrm[j + 3]);
        float4 v0 = bf4_to_f4(hh[(size_t)s0 * 32 + lane]);
        float4 v1 = bf4_to_f4(hh[(size_t)s1 * 32 + lane]);
        float4 v2 = bf4_to_f4(hh[(size_t)s2 * 32 + lane]);
        float4 v3 = bf4_to_f4(hh[(size_t)s3 * 32 + lane]);
        acc.x += v0.x * w0; acc.y += v0.y * w0; acc.z += v0.z * w0; acc.w += v0.w * w0;
        acc.x += v1.x * w1; acc.y += v1.y * w1; acc.z += v1.z * w1; acc.w += v1.w * w1;
        acc.x += v2.x * w2; acc.y += v2.y * w2; acc.z += v2.z * w2; acc.w += v2.w * w2;
        acc.x += v3.x * w3; acc.y += v3.y * w3; acc.z += v3.z * w3; acc.w += v3.w * w3;
    }
    for (; j < end; j++) {
        int   s0 = __ldg(&g_csr_src[j]);
        float w0 = __ldg(&g_csr_nrm[j]);
        float4 v0 = bf4_to_f4(hh[(size_t)s0 * 32 + lane]);
        acc.x += v0.x * w0; acc.y += v0.y * w0; acc.z += v0.z * w0; acc.w += v0.w * w0;
    }

    float4 bb = ((const float4*)b)[lane];
    acc.x = fmaxf(acc.x + bb.x, 0.f);
    acc.y = fmaxf(acc.y + bb.y, 0.f);
    acc.z = fmaxf(acc.z + bb.z, 0.f);
    acc.w = fmaxf(acc.w + bb.w, 0.f);

    if (LAST) {
        int bg = __ldg(&batch[node]);
        float* sp = g_sums + (size_t)bg * D + lane * 4;
        atomicAdd(sp + 0, acc.x);
        atomicAdd(sp + 1, acc.y);
        atomicAdd(sp + 2, acc.z);
        atomicAdd(sp + 3, acc.w);
    } else {
        __nv_bfloat16 hx = cvt_hi(acc.x), hy = cvt_hi(acc.y);
        __nv_bfloat16 hz = cvt_hi(acc.z), hw = cvt_hi(acc.w);
        __nv_bfloat162* xh2 = (__nv_bfloat162*)g_xh;
        __nv_bfloat162* xl2 = (__nv_bfloat162*)g_xl;
        size_t base = (size_t)node * 64 + lane * 2;
        xh2[base + 0] = __nv_bfloat162{hx, hy};
        xh2[base + 1] = __nv_bfloat162{hz, hw};
        xl2[base + 0] = __nv_bfloat162{
            __float2bfloat16(acc.x - __bfloat162float(hx)),
            __float2bfloat16(acc.y - __bfloat162float(hy))};
        xl2[base + 1] = __nv_bfloat162{
            __float2bfloat16(acc.z - __bfloat162float(hz)),
            __float2bfloat16(acc.w - __bfloat162float(hw))};
    }
}

// ----------------- classifier -----------------
__global__ __launch_bounds__(128) void k_classify(const float* __restrict__ Wc,
                                                  const float* __restrict__ bc,
                                                  float* __restrict__ out) {
    __shared__ float s[N_CLASSES];
    int g = blockIdx.x;
    int tid = threadIdx.x;
    if (tid < N_CLASSES) s[tid] = 0.f;
    __syncthreads();
    float cnt = fmaxf(g_cnts[g], 1.0f);
    float p = g_sums[(size_t)g * D + tid] / cnt;
    #pragma unroll
    for (int c = 0; c < N_CLASSES; c++)
        atomicAdd(&s[c], p * Wc[tid * N_CLASSES + c]);
    __syncthreads();
    if (tid < N_CLASSES) out[g * N_CLASSES + tid] = s[tid] + bc[tid];
}

// ---------------------------------------------------------------
extern "C" void kernel_launch(void* const* d_in, const int* in_sizes, int n_in,
                              void* d_out, int out_size) {
    const float* x       = (const float*)d_in[0];
    const int*   e_src   = (const int*)d_in[1];
    const int*   e_dst   = (const int*)d_in[2];
    const int*   batch   = (const int*)d_in[3];
    const float* W0 = (const float*)d_in[4];  const float* b0 = (const float*)d_in[5];
    const float* W1 = (const float*)d_in[6];  const float* b1 = (const float*)d_in[7];
    const float* W2 = (const float*)d_in[8];  const float* b2 = (const float*)d_in[9];
    const float* Wc = (const float*)d_in[10]; const float* bc = (const float*)d_in[11];
    float* out = (float*)d_out;

    const int NB_N  = (N_NODES + 255) / 256;
    const int NB_E  = (N_EDGES + 255) / 256;
    const int NB_NW = (N_NODES * 32 + 255) / 256;
    const int gemm_grid = (N_NODES + M_BLK - 1) / M_BLK;   // 1563

    // Single stream; k_gemm_tc<0> at execution index 3 for ncu verification.
    // (scan2 depends only on scan1; gemm0 depends only on x.)
    k_count_deg<<<NB_E, 256>>>(e_dst);            // 0
    k_scan1<<<N_SCANBLK, SCAN_B>>>();             // 1
    k_scan2<<<1, 256>>>();                        // 2
    k_gemm_tc<0><<<gemm_grid, 256>>>(x, W0);      // 3  <- profiled
    k_scan3<<<NB_N, 256>>>(batch);                // 4
    k_fill<<<NB_E, 256>>>(e_src, e_dst);          // 5

    // ---- layer 0 aggregation ----
    k_gather<0><<<NB_NW, 256>>>(b0, nullptr);     // 6
    // ---- layer 1 ----
    k_gemm_tc<1><<<gemm_grid, 256>>>(nullptr, W1);// 7
    k_gather<0><<<NB_NW, 256>>>(b1, nullptr);     // 8
    // ---- layer 2 (fused mean-pool) ----
    k_gemm_tc<1><<<gemm_grid, 256>>>(nullptr, W2);// 9
    k_gather<1><<<NB_NW, 256>>>(b2, batch);       // 10

    // ---- classifier ----
    k_classify<<<N_GRAPHS, 128>>>(Wc, bc, out);   // 11
}

// round 17
// speedup vs baseline: 1.3092x; 1.0159x over previous
#include <cuda_runtime.h>
#include <cuda_bf16.h>
#include <mma.h>
using namespace nvcuda;

#define N_NODES   100000
#define N_EDGES   1600000
#define D         128
#define N_GRAPHS  512
#define N_CLASSES 10
#define SCAN_B    512
#define N_SCANBLK ((N_NODES + SCAN_B - 1) / SCAN_B)   // 196
#define M_BLK     64
#define KC        64
#define N_PAD     64

// -------- scratch: __device__ globals, referenced ONLY inside device code --------
__device__ __nv_bfloat16  g_hh[(N_NODES + N_PAD) * D];  // h hi (bf16)
__device__ __nv_bfloat16  g_hl[(N_NODES + N_PAD) * D];  // h lo (bf16 residual)
__device__ __nv_bfloat16  g_xh[(N_NODES + N_PAD) * D];  // activation hi
__device__ __nv_bfloat16  g_xl[(N_NODES + N_PAD) * D];  // activation lo
__device__ float g_dinv[N_NODES];
__device__ int   g_deg[N_NODES];
__device__ int   g_cnt[N_NODES];
__device__ int   g_rowex[N_NODES];
__device__ int   g_row[N_NODES + 1];
__device__ int   g_bsum[N_SCANBLK];
__device__ int   g_boff[N_SCANBLK];
__device__ int2  g_csr[N_EDGES];          // packed {src, norm-as-int}
__device__ float g_sums[N_GRAPHS * D];
__device__ float g_cnts[N_GRAPHS];

// ----------------- setup -----------------
__global__ __launch_bounds__(256) void k_count_deg(const int* __restrict__ dst) {
    int e = blockIdx.x * blockDim.x + threadIdx.x;
    if (e < N_EDGES) atomicAdd(&g_deg[dst[e]], 1);
}
__global__ __launch_bounds__(SCAN_B) void k_scan1() {
    __shared__ int s[SCAN_B];
    int tid = threadIdx.x;
    int gid = blockIdx.x * SCAN_B + tid;
    int v = (gid < N_NODES) ? g_deg[gid] : 0;
    if (gid < N_NODES) {
        g_dinv[gid] = rsqrtf((float)v + 1.0f);
        g_deg[gid] = 0;
        g_cnt[gid] = 0;
    }
    s[tid] = v;
    __syncthreads();
    #pragma unroll
    for (int off = 1; off < SCAN_B; off <<= 1) {
        int t = (tid >= off) ? s[tid - off] : 0;
        __syncthreads();
        s[tid] += t;
        __syncthreads();
    }
    if (gid < N_NODES) g_rowex[gid] = s[tid] - v;
    if (tid == SCAN_B - 1) g_bsum[blockIdx.x] = s[tid];
}
__global__ __launch_bounds__(256) void k_scan2() {
    __shared__ int s[256];
    int tid = threadIdx.x;
    int v = (tid < N_SCANBLK) ? g_bsum[tid] : 0;
    s[tid] = v;
    __syncthreads();
    #pragma unroll
    for (int off = 1; off < 256; off <<= 1) {
        int t = (tid >= off) ? s[tid - off] : 0;
        __syncthreads();
        s[tid] += t;
        __syncthreads();
    }
    if (tid < N_SCANBLK) g_boff[tid] = s[tid] - v;
    if (tid == 255) g_row[N_NODES] = s[255];
    for (int i = tid; i < N_GRAPHS * D; i += 256) g_sums[i] = 0.f;
    for (int i = tid; i < N_GRAPHS; i += 256) g_cnts[i] = 0.f;
}
__global__ __launch_bounds__(256) void k_scan3(const int* __restrict__ batch) {
    int i = blockIdx.x * blockDim.x + threadIdx.x;
    if (i < N_NODES) {
        g_row[i] = g_rowex[i] + g_boff[i / SCAN_B];
        atomicAdd(&g_cnts[batch[i]], 1.0f);
    }
}
__global__ __launch_bounds__(256) void k_fill(const int* __restrict__ src,
                                              const int* __restrict__ dst) {
    int e = blockIdx.x * blockDim.x + threadIdx.x;
    if (e >= N_EDGES) return;
    int s = src[e], d = dst[e];
    int idx = g_row[d] + atomicAdd(&g_cnt[d], 1);
    g_csr[idx] = make_int2(s, __float_as_int(g_dinv[s] * g_dinv[d]));
}

// ----------------- helpers -----------------
__device__ __forceinline__ __nv_bfloat16 cvt_hi(float v) { return __float2bfloat16(v); }
__device__ __forceinline__ __nv_bfloat16 cvt_lo(float v) {
    __nv_bfloat16 h = __float2bfloat16(v);
    return __float2bfloat16(v - __bfloat162float(h));
}
__device__ __forceinline__ float4 bf4_to_f4(uint2 u) {
    __nv_bfloat162 a = *(__nv_bfloat162*)&u.x;
    __nv_bfloat162 b = *(__nv_bfloat162*)&u.y;
    float2 fa = __bfloat1622float2(a);
    float2 fb = __bfloat1622float2(b);
    return make_float4(fa.x, fa.y, fb.x, fb.y);
}

// ----------------- tensor-core GEMM (unchanged from 518us version) -----------------
#define SMEM_BYTES 35840
__device__ __forceinline__ void mma_pass(
    const __nv_bfloat16* As, const __nv_bfloat16* Bs,
    wmma::fragment<wmma::accumulator, 16, 16, 16, float> (&acc)[2][2],
    int wm, int wn) {
    #pragma unroll
    for (int kk = 0; kk < KC / 16; kk++) {
        wmma::fragment<wmma::matrix_a, 16, 16, 16, __nv_bfloat16, wmma::row_major> af[2];
        wmma::fragment<wmma::matrix_b, 16, 16, 16, __nv_bfloat16, wmma::row_major> bf[2];
        #pragma unroll
        for (int i = 0; i < 2; i++)
            wmma::load_matrix_sync(af[i], &As[(wm * 32 + i * 16) * (KC + 8) + kk * 16], KC + 8);
        #pragma unroll
        for (int j = 0; j < 2; j++)
            wmma::load_matrix_sync(bf[j], &Bs[(kk * 16) * (D + 8) + wn * 32 + j * 16], D + 8);
        #pragma unroll
        for (int i = 0; i < 2; i++)
            #pragma unroll
            for (int j = 0; j < 2; j++)
                wmma::mma_sync(acc[i][j], af[i], bf[j], acc[i][j]);
    }
}

template <int SRC>
__global__ __launch_bounds__(256, 2) void k_gemm_tc(const float* __restrict__ xf,
                                                    const float* __restrict__ Wf) {
    __shared__ __align__(16) char smem_raw[SMEM_BYTES];
    __nv_bfloat16* Ah = (__nv_bfloat16*)smem_raw;
    __nv_bfloat16* Al = (__nv_bfloat16*)(smem_raw + 9216);
    __nv_bfloat16* Bs = (__nv_bfloat16*)(smem_raw + 18432);
    float* Cs = (float*)smem_raw;
    const int tid = threadIdx.x;
    const int wid = tid >> 5;
    const int wm = wid & 1;
    const int wn = wid >> 1;
    const int row0 = blockIdx.x * M_BLK;

    wmma::fragment<wmma::accumulator, 16, 16, 16, float> acc[2][2];
    #pragma unroll
    for (int i = 0; i < 2; i++)
        #pragma unroll
        for (int j = 0; j < 2; j++)
            wmma::fill_fragment(acc[i][j], 0.0f);

    #pragma unroll 1
    for (int half = 0; half < 2; half++) {
        const int koff = half * KC;

        __syncthreads();
        if (SRC == 0) {
            #pragma unroll
            for (int j = 0; j < 4; j++) {
                int idx = tid + j * 256;
                int r = idx >> 4, g = idx & 15;
                int row = row0 + r;
                float4 xv = (row < N_NODES)
                    ? *(const float4*)&xf[(size_t)row * D + koff + g * 4]
                    : make_float4(0.f, 0.f, 0.f, 0.f);
                *(__nv_bfloat162*)&Ah[r * (KC + 8) + g * 4]     = __nv_bfloat162{cvt_hi(xv.x), cvt_hi(xv.y)};
                *(__nv_bfloat162*)&Ah[r * (KC + 8) + g * 4 + 2] = __nv_bfloat162{cvt_hi(xv.z), cvt_hi(xv.w)};
                *(__nv_bfloat162*)&Al[r * (KC + 8) + g * 4]     = __nv_bfloat162{cvt_lo(xv.x), cvt_lo(xv.y)};
                *(__nv_bfloat162*)&Al[r * (KC + 8) + g * 4 + 2] = __nv_bfloat162{cvt_lo(xv.z), cvt_lo(xv.w)};
            }
        } else {
            #pragma unroll
            for (int j = 0; j < 4; j++) {
                int idx = tid + j * 256;
                int r = idx >> 4, g = idx & 15;
                *(uint2*)&Ah[r * (KC + 8) + g * 4] =
                    *(const uint2*)&g_xh[(size_t)(row0 + r) * D + koff + g * 4];
                *(uint2*)&Al[r * (KC + 8) + g * 4] =
                    *(const uint2*)&g_xl[(size_t)(row0 + r) * D + koff + g * 4];
            }
        }
        #pragma unroll
        for (int j = 0; j < 8; j++) {
            int idx = tid + j * 256;
            int r = idx >> 5, g = idx & 31;
            float4 wv = *(const float4*)&Wf[(size_t)(koff + r) * D + g * 4];
            *(__nv_bfloat162*)&Bs[r * (D + 8) + g * 4]     = __nv_bfloat162{cvt_hi(wv.x), cvt_hi(wv.y)};
            *(__nv_bfloat162*)&Bs[r * (D + 8) + g * 4 + 2] = __nv_bfloat162{cvt_hi(wv.z), cvt_hi(wv.w)};
        }
        __syncthreads();

        mma_pass(Ah, Bs, acc, wm, wn);
        mma_pass(Al, Bs, acc, wm, wn);

        __syncthreads();
        #pragma unroll
        for (int j = 0; j < 8; j++) {
            int idx = tid + j * 256;
            int r = idx >> 5, g = idx & 31;
            float4 wv = *(const float4*)&Wf[(size_t)(koff + r) * D + g * 4];
            *(__nv_bfloat162*)&Bs[r * (D + 8) + g * 4]     = __nv_bfloat162{cvt_lo(wv.x), cvt_lo(wv.y)};
            *(__nv_bfloat162*)&Bs[r * (D + 8) + g * 4 + 2] = __nv_bfloat162{cvt_lo(wv.z), cvt_lo(wv.w)};
        }
        __syncthreads();

        mma_pass(Ah, Bs, acc, wm, wn);
    }

    __syncthreads();
    #pragma unroll
    for (int i = 0; i < 2; i++)
        #pragma unroll
        for (int j = 0; j < 2; j++)
            wmma::store_matrix_sync(&Cs[(wm * 32 + i * 16) * (D + 4) + wn * 32 + j * 16],
                                    acc[i][j], D + 4, wmma::mem_row_major);
    __syncthreads();
    #pragma unroll
    for (int it = 0; it < 8; it++) {
        int idx = tid + it * 256;
        int r = idx >> 5, g = idx & 31;
        float4 v = *(const float4*)&Cs[r * (D + 4) + g * 4];
        __nv_bfloat162 ph0{cvt_hi(v.x), cvt_hi(v.y)}, ph1{cvt_hi(v.z), cvt_hi(v.w)};
        __nv_bfloat162 pl0{cvt_lo(v.x), cvt_lo(v.y)}, pl1{cvt_lo(v.z), cvt_lo(v.w)};
        uint2 uh, ul;
        uh.x = *(unsigned*)&ph0; uh.y = *(unsigned*)&ph1;
        ul.x = *(unsigned*)&pl0; ul.y = *(unsigned*)&pl1;
        *(uint2*)&g_hh[(size_t)(row0 + r) * D + g * 4] = uh;
        *(uint2*)&g_hl[(size_t)(row0 + r) * D + g * 4] = ul;
    }
}

// ----------------- fused aggregation (warp per node, batched edge records) ------------
// R17: one coalesced LDG.64 loads 32 packed {src,nrm} records across lanes; per-edge
// values come from shfl (non-LSU pipe). LDG/edge drops from 3 to ~1.03.
template <int LAST>
__global__ __launch_bounds__(256) void k_gather(const float* __restrict__ b,
                                                const int* __restrict__ batch) {
    int node = (blockIdx.x * blockDim.x + threadIdx.x) >> 5;
    int lane = threadIdx.x & 31;
    if (node >= N_NODES) return;

    const uint2* hh = (const uint2*)g_hh;
    const uint2* hl = (const uint2*)g_hl;
    int beg = g_row[node];
    int end = g_row[node + 1];

    float dv = g_dinv[node];
    float d2 = dv * dv;
    float4 vh = bf4_to_f4(hh[(size_t)node * 32 + lane]);
    float4 vl = bf4_to_f4(hl[(size_t)node * 32 + lane]);
    float4 acc = make_float4(d2 * (vh.x + vl.x), d2 * (vh.y + vl.y),
                             d2 * (vh.z + vl.z), d2 * (vh.w + vl.w));

    for (int base = beg; base < end; base += 32) {
        int m = end - base;
        if (m > 32) m = 32;
        int2 rec = make_int2(0, 0);
        if (lane < m) rec = __ldg(&g_csr[base + lane]);

        int e = 0;
        for (; e + 1 < m; e += 2) {
            int   s0 = __shfl_sync(0xffffffffu, rec.x, e);
            float w0 = __int_as_float(__shfl_sync(0xffffffffu, rec.y, e));
            int   s1 = __shfl_sync(0xffffffffu, rec.x, e + 1);
            float w1 = __int_as_float(__shfl_sync(0xffffffffu, rec.y, e + 1));
            float4 v0 = bf4_to_f4(hh[(size_t)s0 * 32 + lane]);
            float4 v1 = bf4_to_f4(hh[(size_t)s1 * 32 + lane]);
            acc.x += v0.x * w0; acc.y += v0.y * w0; acc.z += v0.z * w0; acc.w += v0.w * w0;
            acc.x += v1.x * w1; acc.y += v1.y * w1; acc.z += v1.z * w1; acc.w += v1.w * w1;
        }
        if (e < m) {
            int   s0 = __shfl_sync(0xffffffffu, rec.x, e);
            float w0 = __int_as_float(__shfl_sync(0xffffffffu, rec.y, e));
            float4 v0 = bf4_to_f4(hh[(size_t)s0 * 32 + lane]);
            acc.x += v0.x * w0; acc.y += v0.y * w0; acc.z += v0.z * w0; acc.w += v0.w * w0;
        }
    }

    float4 bb = ((const float4*)b)[lane];
    acc.x = fmaxf(acc.x + bb.x, 0.f);
    acc.y = fmaxf(acc.y + bb.y, 0.f);
    acc.z = fmaxf(acc.z + bb.z, 0.f);
    acc.w = fmaxf(acc.w + bb.w, 0.f);

    if (LAST) {
        int bg = __ldg(&batch[node]);
        float* sp = g_sums + (size_t)bg * D + lane * 4;
        atomicAdd(sp + 0, acc.x);
        atomicAdd(sp + 1, acc.y);
        atomicAdd(sp + 2, acc.z);
        atomicAdd(sp + 3, acc.w);
    } else {
        __nv_bfloat16 hx = cvt_hi(acc.x), hy = cvt_hi(acc.y);
        __nv_bfloat16 hz = cvt_hi(acc.z), hw = cvt_hi(acc.w);
        __nv_bfloat162* xh2 = (__nv_bfloat162*)g_xh;
        __nv_bfloat162* xl2 = (__nv_bfloat162*)g_xl;
        size_t base2 = (size_t)node * 64 + lane * 2;
        xh2[base2 + 0] = __nv_bfloat162{hx, hy};
        xh2[base2 + 1] = __nv_bfloat162{hz, hw};
        xl2[base2 + 0] = __nv_bfloat162{
            __float2bfloat16(acc.x - __bfloat162float(hx)),
            __float2bfloat16(acc.y - __bfloat162float(hy))};
        xl2[base2 + 1] = __nv_bfloat162{
            __float2bfloat16(acc.z - __bfloat162float(hz)),
            __float2bfloat16(acc.w - __bfloat162float(hw))};
    }
}

// ----------------- classifier -----------------
__global__ __launch_bounds__(128) void k_classify(const float* __restrict__ Wc,
                                                  const float* __restrict__ bc,
                                                  float* __restrict__ out) {
    __shared__ float s[N_CLASSES];
    int g = blockIdx.x;
    int tid = threadIdx.x;
    if (tid < N_CLASSES) s[tid] = 0.f;
    __syncthreads();
    float cnt = fmaxf(g_cnts[g], 1.0f);
    float p = g_sums[(size_t)g * D + tid] / cnt;
    #pragma unroll
    for (int c = 0; c < N_CLASSES; c++)
        atomicAdd(&s[c], p * Wc[tid * N_CLASSES + c]);
    __syncthreads();
    if (tid < N_CLASSES) out[g * N_CLASSES + tid] = s[tid] + bc[tid];
}

// ---------------------------------------------------------------
extern "C" void kernel_launch(void* const* d_in, const int* in_sizes, int n_in,
                              void* d_out, int out_size) {
    const float* x       = (const float*)d_in[0];
    const int*   e_src   = (const int*)d_in[1];
    const int*   e_dst   = (const int*)d_in[2];
    const int*   batch   = (const int*)d_in[3];
    const float* W0 = (const float*)d_in[4];  const float* b0 = (const float*)d_in[5];
    const float* W1 = (const float*)d_in[6];  const float* b1 = (const float*)d_in[7];
    const float* W2 = (const float*)d_in[8];  const float* b2 = (const float*)d_in[9];
    const float* Wc = (const float*)d_in[10]; const float* bc = (const float*)d_in[11];
    float* out = (float*)d_out;

    const int NB_N  = (N_NODES + 255) / 256;
    const int NB_E  = (N_EDGES + 255) / 256;
    const int NB_NW = (N_NODES * 32 + 255) / 256;
    const int gemm_grid = (N_NODES + M_BLK - 1) / M_BLK;   // 1563

    // Single stream; k_gemm_tc<0> at execution index 3 for ncu verification.
    k_count_deg<<<NB_E, 256>>>(e_dst);            // 0
    k_scan1<<<N_SCANBLK, SCAN_B>>>();             // 1
    k_scan2<<<1, 256>>>();                        // 2
    k_gemm_tc<0><<<gemm_grid, 256>>>(x, W0);      // 3  <- profiled
    k_scan3<<<NB_N, 256>>>(batch);                // 4
    k_fill<<<NB_E, 256>>>(e_src, e_dst);          // 5

    // ---- layer 0 aggregation ----
    k_gather<0><<<NB_NW, 256>>>(b0, nullptr);     // 6
    // ---- layer 1 ----
    k_gemm_tc<1><<<gemm_grid, 256>>>(nullptr, W1);// 7
    k_gather<0><<<NB_NW, 256>>>(b1, nullptr);     // 8
    // ---- layer 2 (fused mean-pool) ----
    k_gemm_tc<1><<<gemm_grid, 256>>>(nullptr, W2);// 9
    k_gather<1><<<NB_NW, 256>>>(b2, batch);       // 10

    // ---- classifier ----
    k_classify<<<N_GRAPHS, 128>>>(Wc, bc, out);   // 11
}